// round 17
// baseline (speedup 1.0000x reference)
#include <cuda_runtime.h>
#include <cuda_bf16.h>

// PrototypeLoss: out = mean_i ||features[i] - prototypes[labels[i]]||^2
// N=131072, D=512, C=1000.
//
// R16 falsified the LTS-cap theory (halving proto bytes changed nothing).
// Binder = achieved DRAM bandwidth (~5.75 TB/s = 72%). This round targets
// DRAM row-buffer efficiency: block-contiguous row chunks (888 wide streams
// instead of 7104 interleaved 2KB streams) + __ldcs evict-first on the
// feature stream. f32 prototypes via __ldg (L2-resident, proven).
//
// inputs identified by element count:
//   features f32 [N,D]=67108864, labels int [N]=131072 (dtype sniffed),
//   protos f32 [C,D]=512000.  output: f32 [1,1]

#define N_ROWS 131072
#define N_CLASSES 1000
#define D_VEC  128                 // D/4 float4 per row
#define BLOCKS_PER_SM 6
#define GRID_BLOCKS (148 * BLOCKS_PER_SM)   // 888 = one full wave
#define BLOCK_THREADS 256
#define WARPS_PER_BLOCK (BLOCK_THREADS / 32)
#define CHUNK ((N_ROWS + GRID_BLOCKS - 1) / GRID_BLOCKS)   // 148 rows/block
#define MAX_ITERS ((CHUNK + WARPS_PER_BLOCK - 1) / WARPS_PER_BLOCK)  // 19

__device__ float    g_partials[GRID_BLOCKS];
__device__ unsigned g_done;   // zero-init at load; reset by last block each run

__device__ __forceinline__ float row_dist_partial(const float4* __restrict__ f,
                                                  const float4* __restrict__ p,
                                                  int lane) {
    float acc = 0.0f;
    #pragma unroll
    for (int j = 0; j < 4; j++) {
        const int idx = lane + j * 32;
        float4 a = __ldcs(&f[idx]);   // evict-first: pure stream, keep L2 for protos
        float4 b = __ldg(&p[idx]);    // L2-resident gather
        float dx = a.x - b.x;
        float dy = a.y - b.y;
        float dz = a.z - b.z;
        float dw = a.w - b.w;
        acc = fmaf(dx, dx, acc);
        acc = fmaf(dy, dy, acc);
        acc = fmaf(dz, dz, acc);
        acc = fmaf(dw, dw, acc);
    }
    return acc;
}

__global__ __launch_bounds__(BLOCK_THREADS, BLOCKS_PER_SM)
void proto_loss_kernel(const float4* __restrict__ feat,
                       const void* __restrict__ labels_raw,
                       const float4* __restrict__ protos,
                       float* __restrict__ out) {
    const int lane = threadIdx.x & 31;
    const int wid  = threadIdx.x >> 5;

    __shared__ int   s_is64;
    __shared__ float ssum[WARPS_PER_BLOCK];
    __shared__ int   s_last;

    // --- Label dtype sniff (warp 0): for int64 labels in [0,1000), the odd
    // 32-bit words of the first 64 entries are all zero. For int32 that needs
    // 64 specific labels == 0 (p ~ 1e-192).
    if (wid == 0) {
        const unsigned* lw = (const unsigned*)labels_raw;
        unsigned w = lw[2 * lane + 1] | lw[2 * lane + 65];
        #pragma unroll
        for (int off = 16; off; off >>= 1)
            w |= __shfl_xor_sync(0xFFFFFFFFu, w, off);
        if (lane == 0) s_is64 = (w == 0u) ? 1 : 0;
    }
    __syncthreads();
    const int is64 = s_is64;
    const int*       l32 = (const int*)labels_raw;
    const long long* l64 = (const long long*)labels_raw;

    // Block-contiguous chunk: block owns rows [base, rend); its 8 warps sweep
    // a contiguous window together (16KB instantaneous contiguity).
    const int base = blockIdx.x * CHUNK;
    const int rend = min(base + CHUNK, N_ROWS);

    // --- Preload this warp's labels: lane k holds the label for iteration k
    // (MAX_ITERS=19 <= 32). No label load in the hot loop.
    int mylbl = 0;
    {
        const int myrow = base + wid + lane * WARPS_PER_BLOCK;
        if (lane < MAX_ITERS && myrow < rend) {
            int l = is64 ? (int)l64[myrow] : l32[myrow];
            mylbl = (l < 0) ? 0 : (l >= N_CLASSES ? N_CLASSES - 1 : l);
        }
    }

    float acc = 0.0f;

    #pragma unroll
    for (int it = 0; it < MAX_ITERS; it++) {
        const int row = base + wid + it * WARPS_PER_BLOCK;
        const int lbl = __shfl_sync(0xFFFFFFFFu, mylbl, it);
        if (row < rend) {
            const float4* f = feat   + (size_t)row * D_VEC;
            const float4* p = protos + (size_t)lbl * D_VEC;
            acc += row_dist_partial(f, p, lane);
        }
    }

    // warp reduce
    #pragma unroll
    for (int off = 16; off; off >>= 1)
        acc += __shfl_xor_sync(0xFFFFFFFFu, acc, off);
    if (lane == 0) ssum[wid] = acc;
    __syncthreads();

    // block reduce + publish partial; last block to arrive finishes.
    if (wid == 0) {
        float v = (lane < WARPS_PER_BLOCK) ? ssum[lane] : 0.0f;
        #pragma unroll
        for (int off = 4; off; off >>= 1)
            v += __shfl_xor_sync(0xFFFFFFFFu, v, off);
        if (lane == 0) {
            g_partials[blockIdx.x] = v;
            __threadfence();
            unsigned ticket = atomicAdd(&g_done, 1u);
            s_last = (ticket == GRID_BLOCKS - 1) ? 1 : 0;
        }
    }
    __syncthreads();

    if (s_last) {
        __threadfence();  // all g_partials writes visible
        __shared__ double dsum[WARPS_PER_BLOCK];
        double d = 0.0;
        for (int i = threadIdx.x; i < GRID_BLOCKS; i += BLOCK_THREADS)
            d += (double)g_partials[i];
        #pragma unroll
        for (int off = 16; off; off >>= 1)
            d += __shfl_xor_sync(0xFFFFFFFFu, d, off);
        if (lane == 0) dsum[wid] = d;
        __syncthreads();
        if (wid == 0) {
            double t = (lane < WARPS_PER_BLOCK) ? dsum[lane] : 0.0;
            #pragma unroll
            for (int off = 4; off; off >>= 1)
                t += __shfl_xor_sync(0xFFFFFFFFu, t, off);
            if (lane == 0) {
                out[0] = (float)(t * (1.0 / (double)N_ROWS));
                g_done = 0u;   // reset for next graph replay
            }
        }
    }
}

extern "C" void kernel_launch(void* const* d_in, const int* in_sizes, int n_in,
                              void* d_out, int out_size) {
    const float4* feat   = 0;
    const void*   labels = 0;
    const float4* protos = 0;
    for (int i = 0; i < n_in; i++) {
        if (in_sizes[i] == N_ROWS * 512)          feat   = (const float4*)d_in[i];
        else if (in_sizes[i] == N_CLASSES * 512)  protos = (const float4*)d_in[i];
        else                                      labels = d_in[i];
    }
    float* out = (float*)d_out;

    proto_loss_kernel<<<GRID_BLOCKS, BLOCK_THREADS>>>(feat, labels, protos, out);
}